// round 15
// baseline (speedup 1.0000x reference)
#include <cuda_runtime.h>
#include <cuda_fp16.h>
#include <cstdint>
#include <math.h>

// ---------------------------------------------------------------------------
// Problem dims (fixed)
// ---------------------------------------------------------------------------
#define T_TOK 8192
#define H_DIM 2048
#define I_DIM 1408
#define E_NUM 32

#define SZ_HH ((size_t)T_TOK * I_DIM)

// Scratch (device globals — no allocations allowed anywhere).
__device__ __align__(256) __half g_h16[SZ_HH];   // [T][I] fp16

// ---------------------------------------------------------------------------
// PTX helpers (base-target legal: cp.async / ldmatrix / mma.sync)
// ---------------------------------------------------------------------------
__device__ __forceinline__ uint32_t smem_u32(const void* p) {
    uint32_t a;
    asm("{ .reg .u64 t; cvta.to.shared.u64 t, %1; cvt.u32.u64 %0, t; }"
        : "=r"(a) : "l"(p));
    return a;
}
__device__ __forceinline__ void cpa16(uint32_t s, const void* g) {
    asm volatile("cp.async.cg.shared.global [%0], [%1], 16;" :: "r"(s), "l"(g));
}
#define CP_COMMIT() asm volatile("cp.async.commit_group;" ::: "memory")
#define CP_WAIT1()  asm volatile("cp.async.wait_group 1;" ::: "memory")
#define CP_WAIT0()  asm volatile("cp.async.wait_group 0;" ::: "memory")

__device__ __forceinline__ void ldsm4(uint32_t* r, uint32_t addr) {
    asm volatile("ldmatrix.sync.aligned.m8n8.x4.shared.b16 {%0,%1,%2,%3}, [%4];"
                 : "=r"(r[0]), "=r"(r[1]), "=r"(r[2]), "=r"(r[3]) : "r"(addr));
}
__device__ __forceinline__ void ldsm4t(uint32_t* r, uint32_t addr) {
    asm volatile("ldmatrix.sync.aligned.m8n8.x4.trans.shared.b16 {%0,%1,%2,%3}, [%4];"
                 : "=r"(r[0]), "=r"(r[1]), "=r"(r[2]), "=r"(r[3]) : "r"(addr));
}
__device__ __forceinline__ void mma16816(float* d, const uint32_t* a,
                                         uint32_t b0, uint32_t b1) {
    asm volatile(
        "mma.sync.aligned.m16n8k16.row.col.f32.f16.f16.f32 "
        "{%0,%1,%2,%3}, {%4,%5,%6,%7}, {%8,%9}, {%0,%1,%2,%3};"
        : "+f"(d[0]), "+f"(d[1]), "+f"(d[2]), "+f"(d[3])
        : "r"(a[0]), "r"(a[1]), "r"(a[2]), "r"(a[3]), "r"(b0), "r"(b1));
}
__device__ __forceinline__ uint32_t pkh2(float a, float b) {
    __half2 h = __floats2half2_rn(a, b);
    return *reinterpret_cast<uint32_t*>(&h);
}

// ---------------------------------------------------------------------------
// Shared tile helpers
// ---------------------------------------------------------------------------
#define APLANE 16384      // 128 x 64 fp16
#define A32HB  16384      // 128 x 32 fp32 staging (one k32 half)
#define BPLANE 16384      // 64 x 128 fp16 (two 64-n 8KB halves) — gemm2
#define BPL64  8192       // 64 x 64 fp16 — gemm1

// cp.async A prefetch (gemm2: A = h16 already fp16)
__device__ __forceinline__ void prefetch_a(const __half* A, int K, int k0,
                                           uint32_t st, int tid) {
    #pragma unroll
    for (int p = 0; p < 4; p++) {
        int c   = tid + 256 * p;          // 0..1023
        int row = c >> 3;                 // m 0..127
        int kc  = c & 7;
        uint32_t so = (uint32_t)(row * 128 + ((kc ^ (row & 7)) << 4));
        cpa16(st + so, A + (size_t)row * K + k0 + kc * 8);
    }
}
// ---- gemm1 A: cp.async one k32 half of fp32 x into linear staging ----
// Per-thread byte ownership here MUST match cvt_a32h (same c mapping):
// thread t converts exactly the bytes thread t staged -> no cross-warp race.
__device__ __forceinline__ void ldga32_h(const float* A, int K, int k0, int h,
                                         uint32_t st, int tid) {
    #pragma unroll
    for (int p = 0; p < 4; p++) {
        int c   = tid + 256 * p;          // 0..1023
        int row = c >> 3;                 // m 0..127
        int kc  = c & 7;                  // 16B chunk (4 floats) in k32 half
        cpa16(st + (uint32_t)(c * 16),
              A + (size_t)row * K + k0 + h * 32 + kc * 4);
    }
}
// Convert staged fp32 half -> SW128 fp16 A-plane chunks (same layout as
// prefetch_a writes: 16B fp16 chunk kch at row*128 + ((kch^(row&7))<<4)).
__device__ __forceinline__ void cvt_a32h(const char* stg, char* dst,
                                         int tid, int h) {
    #pragma unroll
    for (int p = 0; p < 4; p++) {
        int c   = tid + 256 * p;
        int row = c >> 3;
        int kc  = c & 7;
        float4 v = *reinterpret_cast<const float4*>(stg + c * 16);
        int kch = h * 4 + (kc >> 1);      // 16B fp16 chunk index in 128B row
        uint32_t off = (uint32_t)(row * 128 +
                                  ((kch ^ (row & 7)) << 4) + (kc & 1) * 8);
        *reinterpret_cast<uint2*>(dst + off) =
            make_uint2(pkh2(v.x, v.y), pkh2(v.z, v.w));
    }
}
// ---- 128-wide B tile (gemm2): one k32 half -> 4 float4 per thread ----
__device__ __forceinline__ void ldg_bhalf(const float* B, int N, int k0, int n0,
                                          int tid, int h, float4* r) {
    #pragma unroll
    for (int p = 0; p < 4; p++) {
        int c   = (h * 4 + p) * 256 + tid;
        int row = c >> 5;
        int ch  = c & 31;
        r[p] = __ldg(reinterpret_cast<const float4*>(
                     B + (size_t)(k0 + row) * N + n0 + ch * 4));
    }
}
__device__ __forceinline__ void sts_bhalf(const float4* r, char* dst, int tid, int h) {
    #pragma unroll
    for (int p = 0; p < 4; p++) {
        int c   = (h * 4 + p) * 256 + tid;
        int row = c >> 5;
        int n   = (c & 31) * 4;
        int hf  = n >> 6;
        int jj  = (n & 63) >> 3;
        uint32_t off = (uint32_t)(hf * 8192 + row * 128 +
                                  ((jj ^ (row & 7)) << 4) + (n & 4) * 2);
        *reinterpret_cast<uint2*>(dst + off) =
            make_uint2(pkh2(r[p].x, r[p].y), pkh2(r[p].z, r[p].w));
    }
}
// ---- 64-wide B tile (gemm1): one k32 half -> 2 float4 per thread ----
__device__ __forceinline__ void ldg_b64h(const float* B, int N, int k0, int n0,
                                         int tid, int h, float4* r) {
    #pragma unroll
    for (int p = 0; p < 2; p++) {
        int c   = (h * 2 + p) * 256 + tid;   // 0..1023
        int row = c >> 4;                    // k 0..63
        int ch  = c & 15;                    // 16B chunk in 64-n row
        r[p] = __ldg(reinterpret_cast<const float4*>(
                     B + (size_t)(k0 + row) * N + n0 + ch * 4));
    }
}
__device__ __forceinline__ void sts_b64h(const float4* r, char* dst, int tid, int h) {
    #pragma unroll
    for (int p = 0; p < 2; p++) {
        int c   = (h * 2 + p) * 256 + tid;
        int row = c >> 4;
        int n   = (c & 15) * 4;              // 0..60
        int jj  = n >> 3;
        uint32_t off = (uint32_t)(row * 128 +
                                  ((jj ^ (row & 7)) << 4) + (n & 4) * 2);
        *reinterpret_cast<uint2*>(dst + off) =
            make_uint2(pkh2(r[p].x, r[p].y), pkh2(r[p].z, r[p].w));
    }
}
// Fragment smem offsets — verified R4-R14.
__device__ __forceinline__ uint32_t b_off(int s, int base_n, int lane) {
    int kRow = s * 16 + (lane & 7) + ((lane >> 4) << 3);
    int nOff = base_n + (((lane >> 3) & 1) << 3);
    int half = nOff >> 6;
    int jj   = (nOff & 63) >> 3;
    return (uint32_t)(half * 8192 + kRow * 128 + ((jj ^ (kRow & 7)) << 4));
}
__device__ __forceinline__ uint32_t a_off(int row, int s, int lhi) {
    int ch = 2 * s + lhi;
    return (uint32_t)(row * 128 + ((ch ^ (row & 7)) << 4));
}

// ---------------------------------------------------------------------------
// GEMM1: fused gate+up + fused x fp32->fp16 convert (no cvt pass).
// CTA 128x64, 2m x 4n, occ 2.  R12 schedule with A staged as fp32 halves:
//   top:  WAIT1 (half0(it+1) landed) ; barrier ; convert half0 ; B LDG h0
//   s0,s1 MMA
//   mid:  WAIT0 (half1(it+1)) ; convert half1 ; B STS h0 ; B LDG h1
//   s2,s3 MMA ; B STS h1
//   end:  cp.async half0(it+2), commit ; half1(it+2), commit
// smem: A16[2] 32K + A32h[2] 32K + Bg16[2] 16K + Bu16[2] 16K = 96 KB.
// ---------------------------------------------------------------------------
#define G1_A16(s) ((s) * APLANE)                       // 0, 16K
#define G1_A32(h) (2 * APLANE + (h) * A32HB)           // 32K, 48K
#define G1_BG(s)  (2 * APLANE + 2 * A32HB + (s) * BPL64)            // 64K, 72K
#define G1_BU(s)  (2 * APLANE + 2 * A32HB + 2 * BPL64 + (s) * BPL64) // 80K, 88K
#define G1_TOTAL  (2 * APLANE + 2 * A32HB + 4 * BPL64) // 98304

__global__ __launch_bounds__(256, 2)
void gemm1_kernel(const float* __restrict__ x, const float* __restrict__ Wg,
                  const float* __restrict__ Wu, const int* __restrict__ offs)
{
    extern __shared__ char smem[];
    const uint32_t sb = smem_u32(smem);
    const int tid  = threadIdx.x;
    const int wid  = tid >> 5;
    const int lane = tid & 31;
    const int wm   = wid & 1;
    const int wn   = wid >> 1;

    const int m0 = blockIdx.y * 128;
    const int n0 = blockIdx.x * 64;
    int e = 0;
    while (offs[e] <= m0) e++;

    const float* A  = x + (size_t)m0 * H_DIM;
    const float* Bg = Wg + (size_t)e * H_DIM * I_DIM;
    const float* Bu = Wu + (size_t)e * H_DIM * I_DIM;

    float accg[4][2][4], accu[4][2][4];
    #pragma unroll
    for (int mf = 0; mf < 4; mf++)
        #pragma unroll
        for (int nf = 0; nf < 2; nf++)
            #pragma unroll
            for (int q = 0; q < 4; q++) { accg[mf][nf][q] = 0.f; accu[mf][nf][q] = 0.f; }

    // Prologue: stage + convert A(0); build B(0); launch A(1) halves.
    ldga32_h(A, H_DIM, 0, 0, sb + G1_A32(0), tid);
    ldga32_h(A, H_DIM, 0, 1, sb + G1_A32(1), tid);
    CP_COMMIT();
    {
        float4 rg[2], ru[2];
        #pragma unroll
        for (int h = 0; h < 2; h++) {
            ldg_b64h(Bg, I_DIM, 0, n0, tid, h, rg);
            ldg_b64h(Bu, I_DIM, 0, n0, tid, h, ru);
            sts_b64h(rg, smem + G1_BG(0), tid, h);
            sts_b64h(ru, smem + G1_BU(0), tid, h);
        }
    }
    CP_WAIT0();                            // A32 halves(0) landed
    cvt_a32h(smem + G1_A32(0), smem + G1_A16(0), tid, 0);
    cvt_a32h(smem + G1_A32(1), smem + G1_A16(0), tid, 1);
    // A(1) halves: two groups (wait1 at loop top = half0 done)
    ldga32_h(A, H_DIM, 64, 0, sb + G1_A32(0), tid); CP_COMMIT();
    ldga32_h(A, H_DIM, 64, 1, sb + G1_A32(1), tid); CP_COMMIT();

    const int l16 = lane & 15;
    const int lhi = lane >> 4;
    const int NIT = H_DIM / 64;   // 32

    for (int it = 0; it < NIT; it++) {
        CP_WAIT1();              // half0(it+1) landed (half1 may be in flight)
        __syncthreads();         // A16(sp), B16(sp) stores visible to all

        const int sp  = it & 1;
        const int spn = 1 - sp;
        const uint32_t stA = sb + G1_A16(sp);
        const uint32_t bgb = sb + G1_BG(sp);
        const uint32_t bub = sb + G1_BU(sp);
        const bool more = (it + 1 < NIT);
        const int k1 = (it + 1) * 64;

        float4 rg[2], ru[2];
        if (more) {
            cvt_a32h(smem + G1_A32(0), smem + G1_A16(spn), tid, 0);
            ldg_b64h(Bg, I_DIM, k1, n0, tid, 0, rg);
            ldg_b64h(Bu, I_DIM, k1, n0, tid, 0, ru);
        }

        #pragma unroll
        for (int s = 0; s < 2; s++) {
            uint32_t a[4][4], bg[4], bu[4];
            #pragma unroll
            for (int mf = 0; mf < 4; mf++)
                ldsm4(a[mf], stA + a_off(wm * 64 + mf * 16 + l16, s, lhi));
            {
                uint32_t off = b_off(s, wn * 16, lane);
                ldsm4t(bg, bgb + off);
                ldsm4t(bu, bub + off);
            }
            #pragma unroll
            for (int mf = 0; mf < 4; mf++)
                #pragma unroll
                for (int nf = 0; nf < 2; nf++) {
                    mma16816(accg[mf][nf], a[mf], bg[nf], bg[nf + 2]);
                    mma16816(accu[mf][nf], a[mf], bu[nf], bu[nf + 2]);
                }
        }

        if (more) {
            CP_WAIT0();          // half1(it+1) landed (>=1 iter + 2 s-steps old)
            cvt_a32h(smem + G1_A32(1), smem + G1_A16(spn), tid, 1);
            sts_b64h(rg, smem + G1_BG(spn), tid, 0);
            sts_b64h(ru, smem + G1_BU(spn), tid, 0);
            ldg_b64h(Bg, I_DIM, k1, n0, tid, 1, rg);
            ldg_b64h(Bu, I_DIM, k1, n0, tid, 1, ru);
        }

        #pragma unroll
        for (int s = 2; s < 4; s++) {
            uint32_t a[4][4], bg[4], bu[4];
            #pragma unroll
            for (int mf = 0; mf < 4; mf++)
                ldsm4(a[mf], stA + a_off(wm * 64 + mf * 16 + l16, s, lhi));
            {
                uint32_t off = b_off(s, wn * 16, lane);
                ldsm4t(bg, bgb + off);
                ldsm4t(bu, bub + off);
            }
            #pragma unroll
            for (int mf = 0; mf < 4; mf++)
                #pragma unroll
                for (int nf = 0; nf < 2; nf++) {
                    mma16816(accg[mf][nf], a[mf], bg[nf], bg[nf + 2]);
                    mma16816(accu[mf][nf], a[mf], bu[nf], bu[nf + 2]);
                }
        }

        if (more) {
            sts_b64h(rg, smem + G1_BG(spn), tid, 1);
            sts_b64h(ru, smem + G1_BU(spn), tid, 1);
        }
        // Launch A(it+2) halves.  Safe without a barrier: cp.async targets
        // exactly the bytes THIS thread converted above (same c mapping).
        if (it + 2 < NIT) {
            ldga32_h(A, H_DIM, (it + 2) * 64, 0, sb + G1_A32(0), tid); CP_COMMIT();
            ldga32_h(A, H_DIM, (it + 2) * 64, 1, sb + G1_A32(1), tid); CP_COMMIT();
        }
    }

    // Epilogue: h = silu(g) * u -> fp16
    const int quad = lane >> 2, tq = lane & 3;
    #pragma unroll
    for (int mf = 0; mf < 4; mf++)
        #pragma unroll
        for (int nf = 0; nf < 2; nf++)
            #pragma unroll
            for (int h = 0; h < 2; h++) {
                int m = m0 + wm * 64 + mf * 16 + quad + h * 8;
                int n = n0 + wn * 16 + nf * 8 + tq * 2;
                float g0 = accg[mf][nf][h * 2 + 0], u0 = accu[mf][nf][h * 2 + 0];
                float g1 = accg[mf][nf][h * 2 + 1], u1 = accu[mf][nf][h * 2 + 1];
                float h0 = (g0 / (1.0f + __expf(-g0))) * u0;
                float h1 = (g1 / (1.0f + __expf(-g1))) * u1;
                *reinterpret_cast<uint32_t*>(g_h16 + (size_t)m * I_DIM + n) = pkh2(h0, h1);
            }
}

// ---------------------------------------------------------------------------
// GEMM2: down proj (R12 config, verified at 518.3: CTA 128x128, 2m x 4n,
// occ 2, triple-A single-barrier schedule, cp.async A from g_h16).
// ---------------------------------------------------------------------------
#define G2_A(s)  ((s) * APLANE)
#define G2_B(s)  (3 * APLANE + (s) * BPLANE)
#define G2_TOTAL (3 * APLANE + 2 * BPLANE)    // 81920

__global__ __launch_bounds__(256, 2)
void gemm2_kernel(const float* __restrict__ Wd, const int* __restrict__ offs,
                  float* __restrict__ out)
{
    extern __shared__ char smem[];
    const uint32_t sb = smem_u32(smem);
    const int tid  = threadIdx.x;
    const int wid  = tid >> 5;
    const int lane = tid & 31;
    const int wm   = wid & 1;          // 0..1, 64 m-rows
    const int wn   = wid >> 1;         // 0..3, 32 n-cols

    const int m0 = blockIdx.y * 128;
    const int n0 = blockIdx.x * 128;
    int e = 0;
    while (offs[e] <= m0) e++;

    const __half* A = g_h16 + (size_t)m0 * I_DIM;
    const float*  B = Wd + (size_t)e * I_DIM * H_DIM;

    float acc[4][4][4];
    #pragma unroll
    for (int mf = 0; mf < 4; mf++)
        #pragma unroll
        for (int nf = 0; nf < 4; nf++)
            #pragma unroll
            for (int q = 0; q < 4; q++) acc[mf][nf][q] = 0.f;

    prefetch_a(A, I_DIM, 0, sb + G2_A(0), tid);  CP_COMMIT();
    prefetch_a(A, I_DIM, 64, sb + G2_A(1), tid); CP_COMMIT();
    {
        float4 r[4];
        #pragma unroll
        for (int h = 0; h < 2; h++) {
            ldg_bhalf(B, H_DIM, 0, n0, tid, h, r);
            sts_bhalf(r, smem + G2_B(0), tid, h);
        }
    }

    const int l16 = lane & 15;
    const int lhi = lane >> 4;
    const int NIT = I_DIM / 64;   // 22

    for (int it = 0; it < NIT; it++) {
        CP_WAIT1();              // A(it) landed
        __syncthreads();         // orders A(it)+B16(it); frees A((it+2)%3)
        if (it + 2 < NIT)
            prefetch_a(A, I_DIM, (it + 2) * 64, sb + G2_A((it + 2) % 3), tid);
        CP_COMMIT();

        const int sp  = it & 1;
        const int spn = 1 - sp;
        const uint32_t stA = sb + G2_A(it % 3);
        const uint32_t bb  = sb + G2_B(sp);
        const bool more = (it + 1 < NIT);

        float4 r[4];
        if (more) ldg_bhalf(B, H_DIM, (it + 1) * 64, n0, tid, 0, r);

        #pragma unroll
        for (int s = 0; s < 2; s++) {
            uint32_t a[4][4], b[2][4];
            #pragma unroll
            for (int mf = 0; mf < 4; mf++)
                ldsm4(a[mf], stA + a_off(wm * 64 + mf * 16 + l16, s, lhi));
            #pragma unroll
            for (int nf2 = 0; nf2 < 2; nf2++)
                ldsm4t(b[nf2], bb + b_off(s, wn * 32 + nf2 * 16, lane));
            #pragma unroll
            for (int mf = 0; mf < 4; mf++)
                #pragma unroll
                for (int nf = 0; nf < 4; nf++) {
                    const int n2 = nf >> 1, p = nf & 1;
                    mma16816(acc[mf][nf], a[mf], b[n2][p], b[n2][p + 2]);
                }
        }

        if (more) {
            sts_bhalf(r, smem + G2_B(spn), tid, 0);
            ldg_bhalf(B, H_DIM, (it + 1) * 64, n0, tid, 1, r);
        }

        #pragma unroll
        for (int s = 2; s < 4; s++) {
            uint32_t a[4][4], b[2][4];
            #pragma unroll
            for (int mf = 0; mf < 4; mf++)
                ldsm4(a[mf], stA + a_off(wm * 64 + mf * 16 + l16, s, lhi));
            #pragma unroll
            for (int nf2 = 0; nf2 < 2; nf2++)
                ldsm4t(b[nf2], bb + b_off(s, wn * 32 + nf2 * 16, lane));
            #pragma unroll
            for (int mf = 0; mf < 4; mf++)
                #pragma unroll
                for (int nf = 0; nf < 4; nf++) {
                    const int n2 = nf >> 1, p = nf & 1;
                    mma16816(acc[mf][nf], a[mf], b[n2][p], b[n2][p + 2]);
                }
        }

        if (more) sts_bhalf(r, smem + G2_B(spn), tid, 1);
    }

    const int quad = lane >> 2, tq = lane & 3;
    #pragma unroll
    for (int mf = 0; mf < 4; mf++)
        #pragma unroll
        for (int nf = 0; nf < 4; nf++)
            #pragma unroll
            for (int h = 0; h < 2; h++) {
                int m = m0 + wm * 64 + mf * 16 + quad + h * 8;
                int n = n0 + wn * 32 + nf * 8 + tq * 2;
                *reinterpret_cast<float2*>(out + (size_t)m * H_DIM + n) =
                    make_float2(acc[mf][nf][h * 2 + 0], acc[mf][nf][h * 2 + 1]);
            }
}

// ---------------------------------------------------------------------------
extern "C" void kernel_launch(void* const* d_in, const int* in_sizes, int n_in,
                              void* d_out, int out_size)
{
    const float* x    = (const float*)d_in[0];   // [T, H]
    const float* Wg   = (const float*)d_in[1];   // [E, H, I]
    const float* Wu   = (const float*)d_in[2];   // [E, H, I]
    const float* Wd   = (const float*)d_in[3];   // [E, I, H]
    const int*   offs = (const int*)  d_in[4];   // [E]
    float*       out  = (float*)d_out;           // [T, H]

    cudaFuncSetAttribute(gemm1_kernel, cudaFuncAttributeMaxDynamicSharedMemorySize, G1_TOTAL);
    cudaFuncSetAttribute(gemm2_kernel, cudaFuncAttributeMaxDynamicSharedMemorySize, G2_TOTAL);

    // No conversion prologue: gemm1 stages fp32 x via cp.async and converts
    // in smem one iteration ahead (R6 schedule, R12 tiles).
    gemm1_kernel<<<dim3(I_DIM / 64, T_TOK / 128), 256, G1_TOTAL>>>(x, Wg, Wu, offs);
    gemm2_kernel<<<dim3(H_DIM / 128, T_TOK / 128), 256, G2_TOTAL>>>(Wd, offs, out);
}

// round 16
// speedup vs baseline: 1.1454x; 1.1454x over previous
#include <cuda_runtime.h>
#include <cuda_fp16.h>
#include <cstdint>
#include <math.h>

// ---------------------------------------------------------------------------
// Problem dims (fixed)
// ---------------------------------------------------------------------------
#define T_TOK 8192
#define H_DIM 2048
#define I_DIM 1408
#define E_NUM 32

#define SZ_X ((size_t)T_TOK * H_DIM)
#define SZ_HH ((size_t)T_TOK * I_DIM)

// Scratch (device globals — no allocations allowed anywhere).
__device__ __align__(256) __half g_x16[SZ_X];    // [T][H] fp16
__device__ __align__(256) __half g_h16[SZ_HH];   // [T][I] fp16

// ---------------------------------------------------------------------------
// PTX helpers (base-target legal: cp.async / ldmatrix / mma.sync)
// ---------------------------------------------------------------------------
__device__ __forceinline__ uint32_t smem_u32(const void* p) {
    uint32_t a;
    asm("{ .reg .u64 t; cvta.to.shared.u64 t, %1; cvt.u32.u64 %0, t; }"
        : "=r"(a) : "l"(p));
    return a;
}
__device__ __forceinline__ void cpa16(uint32_t s, const void* g) {
    asm volatile("cp.async.cg.shared.global [%0], [%1], 16;" :: "r"(s), "l"(g));
}
#define CP_COMMIT() asm volatile("cp.async.commit_group;" ::: "memory")
#define CP_WAIT1()  asm volatile("cp.async.wait_group 1;" ::: "memory")

__device__ __forceinline__ void ldsm4(uint32_t* r, uint32_t addr) {
    asm volatile("ldmatrix.sync.aligned.m8n8.x4.shared.b16 {%0,%1,%2,%3}, [%4];"
                 : "=r"(r[0]), "=r"(r[1]), "=r"(r[2]), "=r"(r[3]) : "r"(addr));
}
__device__ __forceinline__ void ldsm4t(uint32_t* r, uint32_t addr) {
    asm volatile("ldmatrix.sync.aligned.m8n8.x4.trans.shared.b16 {%0,%1,%2,%3}, [%4];"
                 : "=r"(r[0]), "=r"(r[1]), "=r"(r[2]), "=r"(r[3]) : "r"(addr));
}
__device__ __forceinline__ void mma16816(float* d, const uint32_t* a,
                                         uint32_t b0, uint32_t b1) {
    asm volatile(
        "mma.sync.aligned.m16n8k16.row.col.f32.f16.f16.f32 "
        "{%0,%1,%2,%3}, {%4,%5,%6,%7}, {%8,%9}, {%0,%1,%2,%3};"
        : "+f"(d[0]), "+f"(d[1]), "+f"(d[2]), "+f"(d[3])
        : "r"(a[0]), "r"(a[1]), "r"(a[2]), "r"(a[3]), "r"(b0), "r"(b1));
}
__device__ __forceinline__ uint32_t pkh2(float a, float b) {
    __half2 h = __floats2half2_rn(a, b);
    return *reinterpret_cast<uint32_t*>(&h);
}

// ---------------------------------------------------------------------------
// Prologue: fp32 -> fp16 for x only (weights convert inside the GEMMs).
// Runs at its DRAM floor (~14us for 100MB); cheapest possible location for
// this conversion (fusing into gemm1 measured -75..-95us, R13/R15).
// ---------------------------------------------------------------------------
__global__ __launch_bounds__(256)
void cvt_kernel(const float* __restrict__ src, __half* __restrict__ dst)
{
    size_t i = ((size_t)blockIdx.x * 256 + threadIdx.x) * 8;
    float4 v0 = *reinterpret_cast<const float4*>(src + i);
    float4 v1 = *reinterpret_cast<const float4*>(src + i + 4);
    uint4 o;
    o.x = pkh2(v0.x, v0.y);
    o.y = pkh2(v0.z, v0.w);
    o.z = pkh2(v1.x, v1.y);
    o.w = pkh2(v1.z, v1.w);
    *reinterpret_cast<uint4*>(dst + i) = o;
}

// ---------------------------------------------------------------------------
// Shared tile helpers (verified R4-R14)
// A: fp16 [M,K] k-contig; cp.async into SW128-swizzled fp16 plane (128x64).
// B: fp32 [K,N] n-contig (native); LDG.128 -> regs -> fp16 -> STS (SW128).
// ---------------------------------------------------------------------------
#define APLANE 16384      // 128 x 64 fp16
#define BPLANE 16384      // 64 x 128 fp16 (two 64-n 8KB halves) — gemm2
#define BPL64  8192       // 64 x 64 fp16 — gemm1

__device__ __forceinline__ void prefetch_a(const __half* A, int K, int k0,
                                           uint32_t st, int tid) {
    #pragma unroll
    for (int p = 0; p < 4; p++) {
        int c   = tid + 256 * p;          // 0..1023
        int row = c >> 3;                 // m 0..127
        int kc  = c & 7;
        uint32_t so = (uint32_t)(row * 128 + ((kc ^ (row & 7)) << 4));
        cpa16(st + so, A + (size_t)row * K + k0 + kc * 8);
    }
}
// ---- 128-wide B tile (gemm2): one k32 half -> 4 float4 per thread ----
__device__ __forceinline__ void ldg_bhalf(const float* B, int N, int k0, int n0,
                                          int tid, int h, float4* r) {
    #pragma unroll
    for (int p = 0; p < 4; p++) {
        int c   = (h * 4 + p) * 256 + tid;
        int row = c >> 5;
        int ch  = c & 31;
        r[p] = __ldg(reinterpret_cast<const float4*>(
                     B + (size_t)(k0 + row) * N + n0 + ch * 4));
    }
}
__device__ __forceinline__ void sts_bhalf(const float4* r, char* dst, int tid, int h) {
    #pragma unroll
    for (int p = 0; p < 4; p++) {
        int c   = (h * 4 + p) * 256 + tid;
        int row = c >> 5;
        int n   = (c & 31) * 4;
        int hf  = n >> 6;
        int jj  = (n & 63) >> 3;
        uint32_t off = (uint32_t)(hf * 8192 + row * 128 +
                                  ((jj ^ (row & 7)) << 4) + (n & 4) * 2);
        *reinterpret_cast<uint2*>(dst + off) =
            make_uint2(pkh2(r[p].x, r[p].y), pkh2(r[p].z, r[p].w));
    }
}
// ---- 64-wide B tile (gemm1): one k32 half -> 2 float4 per thread ----
__device__ __forceinline__ void ldg_b64h(const float* B, int N, int k0, int n0,
                                         int tid, int h, float4* r) {
    #pragma unroll
    for (int p = 0; p < 2; p++) {
        int c   = (h * 2 + p) * 256 + tid;   // 0..1023
        int row = c >> 4;                    // k 0..63
        int ch  = c & 15;                    // 16B chunk in 64-n row
        r[p] = __ldg(reinterpret_cast<const float4*>(
                     B + (size_t)(k0 + row) * N + n0 + ch * 4));
    }
}
__device__ __forceinline__ void sts_b64h(const float4* r, char* dst, int tid, int h) {
    #pragma unroll
    for (int p = 0; p < 2; p++) {
        int c   = (h * 2 + p) * 256 + tid;
        int row = c >> 4;
        int n   = (c & 15) * 4;              // 0..60
        int jj  = n >> 3;
        uint32_t off = (uint32_t)(row * 128 +
                                  ((jj ^ (row & 7)) << 4) + (n & 4) * 2);
        *reinterpret_cast<uint2*>(dst + off) =
            make_uint2(pkh2(r[p].x, r[p].y), pkh2(r[p].z, r[p].w));
    }
}
// Fragment smem offsets — verified R4-R14.
__device__ __forceinline__ uint32_t b_off(int s, int base_n, int lane) {
    int kRow = s * 16 + (lane & 7) + ((lane >> 4) << 3);
    int nOff = base_n + (((lane >> 3) & 1) << 3);
    int half = nOff >> 6;
    int jj   = (nOff & 63) >> 3;
    return (uint32_t)(half * 8192 + kRow * 128 + ((jj ^ (kRow & 7)) << 4));
}
__device__ __forceinline__ uint32_t a_off(int row, int s, int lhi) {
    int ch = 2 * s + lhi;
    return (uint32_t)(row * 128 + ((ch ^ (row & 7)) << 4));
}

// ---------------------------------------------------------------------------
// GEMM1: fused gate+up (best config: CTA 128x64, 2m x 4n, occ 2,
// triple-A single-barrier schedule, cp.async A from g_x16).
// ---------------------------------------------------------------------------
#define G1_A(s)  ((s) * APLANE)
#define G1_BG(s) (3 * APLANE + (s) * BPL64)
#define G1_BU(s) (3 * APLANE + 2 * BPL64 + (s) * BPL64)
#define G1_TOTAL (3 * APLANE + 4 * BPL64)     // 81920

__global__ __launch_bounds__(256, 2)
void gemm1_kernel(const float* __restrict__ Wg, const float* __restrict__ Wu,
                  const int* __restrict__ offs)
{
    extern __shared__ char smem[];
    const uint32_t sb = smem_u32(smem);
    const int tid  = threadIdx.x;
    const int wid  = tid >> 5;
    const int lane = tid & 31;
    const int wm   = wid & 1;
    const int wn   = wid >> 1;

    const int m0 = blockIdx.y * 128;
    const int n0 = blockIdx.x * 64;
    int e = 0;
    while (offs[e] <= m0) e++;

    const __half* A  = g_x16 + (size_t)m0 * H_DIM;
    const float*  Bg = Wg + (size_t)e * H_DIM * I_DIM;
    const float*  Bu = Wu + (size_t)e * H_DIM * I_DIM;

    float accg[4][2][4], accu[4][2][4];
    #pragma unroll
    for (int mf = 0; mf < 4; mf++)
        #pragma unroll
        for (int nf = 0; nf < 2; nf++)
            #pragma unroll
            for (int q = 0; q < 4; q++) { accg[mf][nf][q] = 0.f; accu[mf][nf][q] = 0.f; }

    prefetch_a(A, H_DIM, 0, sb + G1_A(0), tid);  CP_COMMIT();
    prefetch_a(A, H_DIM, 64, sb + G1_A(1), tid); CP_COMMIT();
    {
        float4 rg[2], ru[2];
        #pragma unroll
        for (int h = 0; h < 2; h++) {
            ldg_b64h(Bg, I_DIM, 0, n0, tid, h, rg);
            ldg_b64h(Bu, I_DIM, 0, n0, tid, h, ru);
            sts_b64h(rg, smem + G1_BG(0), tid, h);
            sts_b64h(ru, smem + G1_BU(0), tid, h);
        }
    }

    const int l16 = lane & 15;
    const int lhi = lane >> 4;
    const int NIT = H_DIM / 64;   // 32

    for (int it = 0; it < NIT; it++) {
        CP_WAIT1();
        __syncthreads();
        if (it + 2 < NIT)
            prefetch_a(A, H_DIM, (it + 2) * 64, sb + G1_A((it + 2) % 3), tid);
        CP_COMMIT();

        const int sp  = it & 1;
        const int spn = 1 - sp;
        const uint32_t stA = sb + G1_A(it % 3);
        const uint32_t bgb = sb + G1_BG(sp);
        const uint32_t bub = sb + G1_BU(sp);
        const bool more = (it + 1 < NIT);

        float4 rg[2], ru[2];
        if (more) {
            ldg_b64h(Bg, I_DIM, (it + 1) * 64, n0, tid, 0, rg);
            ldg_b64h(Bu, I_DIM, (it + 1) * 64, n0, tid, 0, ru);
        }

        #pragma unroll
        for (int s = 0; s < 2; s++) {
            uint32_t a[4][4], bg[4], bu[4];
            #pragma unroll
            for (int mf = 0; mf < 4; mf++)
                ldsm4(a[mf], stA + a_off(wm * 64 + mf * 16 + l16, s, lhi));
            {
                uint32_t off = b_off(s, wn * 16, lane);
                ldsm4t(bg, bgb + off);
                ldsm4t(bu, bub + off);
            }
            #pragma unroll
            for (int mf = 0; mf < 4; mf++)
                #pragma unroll
                for (int nf = 0; nf < 2; nf++) {
                    mma16816(accg[mf][nf], a[mf], bg[nf], bg[nf + 2]);
                    mma16816(accu[mf][nf], a[mf], bu[nf], bu[nf + 2]);
                }
        }

        if (more) {
            sts_b64h(rg, smem + G1_BG(spn), tid, 0);
            sts_b64h(ru, smem + G1_BU(spn), tid, 0);
            ldg_b64h(Bg, I_DIM, (it + 1) * 64, n0, tid, 1, rg);
            ldg_b64h(Bu, I_DIM, (it + 1) * 64, n0, tid, 1, ru);
        }

        #pragma unroll
        for (int s = 2; s < 4; s++) {
            uint32_t a[4][4], bg[4], bu[4];
            #pragma unroll
            for (int mf = 0; mf < 4; mf++)
                ldsm4(a[mf], stA + a_off(wm * 64 + mf * 16 + l16, s, lhi));
            {
                uint32_t off = b_off(s, wn * 16, lane);
                ldsm4t(bg, bgb + off);
                ldsm4t(bu, bub + off);
            }
            #pragma unroll
            for (int mf = 0; mf < 4; mf++)
                #pragma unroll
                for (int nf = 0; nf < 2; nf++) {
                    mma16816(accg[mf][nf], a[mf], bg[nf], bg[nf + 2]);
                    mma16816(accu[mf][nf], a[mf], bu[nf], bu[nf + 2]);
                }
        }

        if (more) {
            sts_b64h(rg, smem + G1_BG(spn), tid, 1);
            sts_b64h(ru, smem + G1_BU(spn), tid, 1);
        }
    }

    const int quad = lane >> 2, tq = lane & 3;
    #pragma unroll
    for (int mf = 0; mf < 4; mf++)
        #pragma unroll
        for (int nf = 0; nf < 2; nf++)
            #pragma unroll
            for (int h = 0; h < 2; h++) {
                int m = m0 + wm * 64 + mf * 16 + quad + h * 8;
                int n = n0 + wn * 16 + nf * 8 + tq * 2;
                float g0 = accg[mf][nf][h * 2 + 0], u0 = accu[mf][nf][h * 2 + 0];
                float g1 = accg[mf][nf][h * 2 + 1], u1 = accu[mf][nf][h * 2 + 1];
                float h0 = (g0 / (1.0f + __expf(-g0))) * u0;
                float h1 = (g1 / (1.0f + __expf(-g1))) * u1;
                *reinterpret_cast<uint32_t*>(g_h16 + (size_t)m * I_DIM + n) = pkh2(h0, h1);
            }
}

// ---------------------------------------------------------------------------
// GEMM2: down proj (best config: CTA 128x128, 2m x 4n, occ 2,
// triple-A single-barrier schedule, cp.async A from g_h16).
// ---------------------------------------------------------------------------
#define G2_A(s)  ((s) * APLANE)
#define G2_B(s)  (3 * APLANE + (s) * BPLANE)
#define G2_TOTAL (3 * APLANE + 2 * BPLANE)    // 81920

__global__ __launch_bounds__(256, 2)
void gemm2_kernel(const float* __restrict__ Wd, const int* __restrict__ offs,
                  float* __restrict__ out)
{
    extern __shared__ char smem[];
    const uint32_t sb = smem_u32(smem);
    const int tid  = threadIdx.x;
    const int wid  = tid >> 5;
    const int lane = tid & 31;
    const int wm   = wid & 1;          // 0..1, 64 m-rows
    const int wn   = wid >> 1;         // 0..3, 32 n-cols

    const int m0 = blockIdx.y * 128;
    const int n0 = blockIdx.x * 128;
    int e = 0;
    while (offs[e] <= m0) e++;

    const __half* A = g_h16 + (size_t)m0 * I_DIM;
    const float*  B = Wd + (size_t)e * I_DIM * H_DIM;

    float acc[4][4][4];
    #pragma unroll
    for (int mf = 0; mf < 4; mf++)
        #pragma unroll
        for (int nf = 0; nf < 4; nf++)
            #pragma unroll
            for (int q = 0; q < 4; q++) acc[mf][nf][q] = 0.f;

    prefetch_a(A, I_DIM, 0, sb + G2_A(0), tid);  CP_COMMIT();
    prefetch_a(A, I_DIM, 64, sb + G2_A(1), tid); CP_COMMIT();
    {
        float4 r[4];
        #pragma unroll
        for (int h = 0; h < 2; h++) {
            ldg_bhalf(B, H_DIM, 0, n0, tid, h, r);
            sts_bhalf(r, smem + G2_B(0), tid, h);
        }
    }

    const int l16 = lane & 15;
    const int lhi = lane >> 4;
    const int NIT = I_DIM / 64;   // 22

    for (int it = 0; it < NIT; it++) {
        CP_WAIT1();              // A(it) landed
        __syncthreads();         // orders A(it)+B16(it); frees A((it+2)%3)
        if (it + 2 < NIT)
            prefetch_a(A, I_DIM, (it + 2) * 64, sb + G2_A((it + 2) % 3), tid);
        CP_COMMIT();

        const int sp  = it & 1;
        const int spn = 1 - sp;
        const uint32_t stA = sb + G2_A(it % 3);
        const uint32_t bb  = sb + G2_B(sp);
        const bool more = (it + 1 < NIT);

        float4 r[4];
        if (more) ldg_bhalf(B, H_DIM, (it + 1) * 64, n0, tid, 0, r);

        #pragma unroll
        for (int s = 0; s < 2; s++) {
            uint32_t a[4][4], b[2][4];
            #pragma unroll
            for (int mf = 0; mf < 4; mf++)
                ldsm4(a[mf], stA + a_off(wm * 64 + mf * 16 + l16, s, lhi));
            #pragma unroll
            for (int nf2 = 0; nf2 < 2; nf2++)
                ldsm4t(b[nf2], bb + b_off(s, wn * 32 + nf2 * 16, lane));
            #pragma unroll
            for (int mf = 0; mf < 4; mf++)
                #pragma unroll
                for (int nf = 0; nf < 4; nf++) {
                    const int n2 = nf >> 1, p = nf & 1;
                    mma16816(acc[mf][nf], a[mf], b[n2][p], b[n2][p + 2]);
                }
        }

        if (more) {
            sts_bhalf(r, smem + G2_B(spn), tid, 0);
            ldg_bhalf(B, H_DIM, (it + 1) * 64, n0, tid, 1, r);
        }

        #pragma unroll
        for (int s = 2; s < 4; s++) {
            uint32_t a[4][4], b[2][4];
            #pragma unroll
            for (int mf = 0; mf < 4; mf++)
                ldsm4(a[mf], stA + a_off(wm * 64 + mf * 16 + l16, s, lhi));
            #pragma unroll
            for (int nf2 = 0; nf2 < 2; nf2++)
                ldsm4t(b[nf2], bb + b_off(s, wn * 32 + nf2 * 16, lane));
            #pragma unroll
            for (int mf = 0; mf < 4; mf++)
                #pragma unroll
                for (int nf = 0; nf < 4; nf++) {
                    const int n2 = nf >> 1, p = nf & 1;
                    mma16816(acc[mf][nf], a[mf], b[n2][p], b[n2][p + 2]);
                }
        }

        if (more) sts_bhalf(r, smem + G2_B(spn), tid, 1);
    }

    const int quad = lane >> 2, tq = lane & 3;
    #pragma unroll
    for (int mf = 0; mf < 4; mf++)
        #pragma unroll
        for (int nf = 0; nf < 4; nf++)
            #pragma unroll
            for (int h = 0; h < 2; h++) {
                int m = m0 + wm * 64 + mf * 16 + quad + h * 8;
                int n = n0 + wn * 32 + nf * 8 + tq * 2;
                *reinterpret_cast<float2*>(out + (size_t)m * H_DIM + n) =
                    make_float2(acc[mf][nf][h * 2 + 0], acc[mf][nf][h * 2 + 1]);
            }
}

// ---------------------------------------------------------------------------
extern "C" void kernel_launch(void* const* d_in, const int* in_sizes, int n_in,
                              void* d_out, int out_size)
{
    const float* x    = (const float*)d_in[0];   // [T, H]
    const float* Wg   = (const float*)d_in[1];   // [E, H, I]
    const float* Wu   = (const float*)d_in[2];   // [E, H, I]
    const float* Wd   = (const float*)d_in[3];   // [E, I, H]
    const int*   offs = (const int*)  d_in[4];   // [E]
    float*       out  = (float*)d_out;           // [T, H]

    __half* x16;
    cudaGetSymbolAddress((void**)&x16, g_x16);

    cudaFuncSetAttribute(gemm1_kernel, cudaFuncAttributeMaxDynamicSharedMemorySize, G1_TOTAL);
    cudaFuncSetAttribute(gemm2_kernel, cudaFuncAttributeMaxDynamicSharedMemorySize, G2_TOTAL);

    cvt_kernel<<<(int)(SZ_X / 2048), 256>>>(x, x16);

    gemm1_kernel<<<dim3(I_DIM / 64, T_TOK / 128), 256, G1_TOTAL>>>(Wg, Wu, offs);
    gemm2_kernel<<<dim3(H_DIM / 128, T_TOK / 128), 256, G2_TOTAL>>>(Wd, offs, out);
}